// round 5
// baseline (speedup 1.0000x reference)
#include <cuda_runtime.h>
#include <cuda_bf16.h>

typedef unsigned long long u64;

// ---- packed f32x2 helpers (sm_103a; ptxas never auto-fuses these) ----
__device__ __forceinline__ u64 pk2(float lo, float hi) {
    u64 r; asm("mov.b64 %0, {%1, %2};" : "=l"(r) : "f"(lo), "f"(hi)); return r;
}
__device__ __forceinline__ void upk2(u64 x, float& lo, float& hi) {
    asm("mov.b64 {%0, %1}, %2;" : "=f"(lo), "=f"(hi) : "l"(x));
}
__device__ __forceinline__ u64 f2fma(u64 a, u64 b, u64 c) {
    u64 d; asm("fma.rn.f32x2 %0, %1, %2, %3;" : "=l"(d) : "l"(a), "l"(b), "l"(c)); return d;
}
__device__ __forceinline__ u64 f2add(u64 a, u64 b) {
    u64 d; asm("add.rn.f32x2 %0, %1, %2;" : "=l"(d) : "l"(a), "l"(b)); return d;
}
__device__ __forceinline__ u64 f2mul(u64 a, u64 b) {
    u64 d; asm("mul.rn.f32x2 %0, %1, %2;" : "=l"(d) : "l"(a), "l"(b)); return d;
}

constexpr int B_SIZE  = 65536;
constexpr int T_STEPS = 512;
constexpr int THREADS = 128;

// Bloch RHS (params[:,1] unused, matching reference):
//   du = -g*u
//   dv = -g*v - Om*w
//   dw = -2g*(w+1) + Om*v  =  Om*v + (-2g)*w + (-2g)
//
// One thread integrates 2 adjacent particles packed into f32x2 lanes.
__global__ __launch_bounds__(THREADS) void bloch_rk4_kernel(
    const float* __restrict__ y0,
    const float* __restrict__ t_span,
    const float* __restrict__ params,
    float* __restrict__ out)
{
    __shared__ float s_dt[T_STEPS - 1];
    for (int i = threadIdx.x; i < T_STEPS - 1; i += THREADS)
        s_dt[i] = t_span[i + 1] - t_span[i];
    __syncthreads();

    const int tid  = blockIdx.x * THREADS + threadIdx.x;
    const int base = tid * 2;                  // first of this thread's 2 particles

    // Load y0 (6 floats, 8B-aligned) and params (6 floats) as float2
    const float2* y02 = (const float2*)(y0 + (size_t)base * 3);
    float2 a0 = y02[0], a1 = y02[1], a2 = y02[2];
    const float2* pp  = (const float2*)(params + (size_t)base * 3);
    float2 p0 = pp[0], p1 = pp[1], p2 = pp[2];
    // particle0: u=a0.x v=a0.y w=a1.x  Om=p0.x g=p1.x
    // particle1: u=a1.y v=a2.x w=a2.y  Om=p1.y g=p2.y

    u64 u   = pk2(a0.x, a1.y);
    u64 v   = pk2(a0.y, a2.x);
    u64 w   = pk2(a1.x, a2.y);
    u64 Om  = pk2(p0.x, p1.y);
    u64 mOm = pk2(-p0.x, -p1.y);
    u64 ng  = pk2(-p1.x, -p2.y);               // -gamma
    u64 tg  = pk2(-2.0f * p1.x, -2.0f * p2.y); // -2*gamma (slope AND constant term)
    const u64 TWO = pk2(2.0f, 2.0f);

    // t = 0 row: passthrough copy of y0
    {
        float2* o = (float2*)(out + (size_t)base * 3);
        o[0] = a0; o[1] = a1; o[2] = a2;
    }

    float* orow = out + (size_t)B_SIZE * 3 + (size_t)base * 3;

    for (int t = 0; t < T_STEPS - 1; t++) {
        const float dt = s_dt[t];
        const float h  = 0.5f * dt;
        const float d6 = dt * (1.0f / 6.0f);
        const u64 DT = pk2(dt, dt);
        const u64 H  = pk2(h,  h);
        const u64 D6 = pk2(d6, d6);

        // k1 = f(y)
        u64 k1u = f2mul(ng, u);
        u64 k1v = f2fma(ng, v, f2mul(mOm, w));
        u64 k1w = f2fma(Om, v, f2fma(tg, w, tg));
        // k2 = f(y + h*k1)
        u64 u2 = f2fma(H, k1u, u);
        u64 v2 = f2fma(H, k1v, v);
        u64 w2 = f2fma(H, k1w, w);
        u64 k2u = f2mul(ng, u2);
        u64 k2v = f2fma(ng, v2, f2mul(mOm, w2));
        u64 k2w = f2fma(Om, v2, f2fma(tg, w2, tg));
        // k3 = f(y + h*k2)
        u64 u3 = f2fma(H, k2u, u);
        u64 v3 = f2fma(H, k2v, v);
        u64 w3 = f2fma(H, k2w, w);
        u64 k3u = f2mul(ng, u3);
        u64 k3v = f2fma(ng, v3, f2mul(mOm, w3));
        u64 k3w = f2fma(Om, v3, f2fma(tg, w3, tg));
        // k4 = f(y + dt*k3)
        u64 u4 = f2fma(DT, k3u, u);
        u64 v4 = f2fma(DT, k3v, v);
        u64 w4 = f2fma(DT, k3w, w);
        u64 k4u = f2mul(ng, u4);
        u64 k4v = f2fma(ng, v4, f2mul(mOm, w4));
        u64 k4w = f2fma(Om, v4, f2fma(tg, w4, tg));

        // y += dt/6 * (k1 + 2*(k2+k3) + k4)
        u64 su = f2fma(TWO, f2add(k2u, k3u), f2add(k1u, k4u));
        u64 sv = f2fma(TWO, f2add(k2v, k3v), f2add(k1v, k4v));
        u64 sw = f2fma(TWO, f2add(k2w, k3w), f2add(k1w, k4w));
        u = f2fma(D6, su, u);
        v = f2fma(D6, sv, v);
        w = f2fma(D6, sw, w);

        // store [u0,v0,w0,u1,v1,w1] — 24B contiguous, 8-aligned → 3x STG.64
        float uu0, uu1, vv0, vv1, ww0, ww1;
        upk2(u, uu0, uu1);
        upk2(v, vv0, vv1);
        upk2(w, ww0, ww1);
        float2* o = (float2*)orow;
        o[0] = make_float2(uu0, vv0);
        o[1] = make_float2(ww0, uu1);
        o[2] = make_float2(vv1, ww1);
        orow += (size_t)B_SIZE * 3;
    }
}

extern "C" void kernel_launch(void* const* d_in, const int* in_sizes, int n_in,
                              void* d_out, int out_size) {
    const float* y0     = (const float*)d_in[0];
    const float* t_span = (const float*)d_in[1];
    const float* params = (const float*)d_in[2];
    float* out          = (float*)d_out;

    const int total_threads = B_SIZE / 2;          // 32768 (2 particles/thread)
    const int grid = total_threads / THREADS;      // 256 blocks
    bloch_rk4_kernel<<<grid, THREADS>>>(y0, t_span, params, out);
}

// round 6
// speedup vs baseline: 1.3104x; 1.3104x over previous
#include <cuda_runtime.h>
#include <cuda_bf16.h>

typedef unsigned long long u64;

// ---- packed f32x2 helpers (sm_103a; ptxas never auto-fuses these) ----
__device__ __forceinline__ u64 pk2(float lo, float hi) {
    u64 r; asm("mov.b64 %0, {%1, %2};" : "=l"(r) : "f"(lo), "f"(hi)); return r;
}
__device__ __forceinline__ void upk2(u64 x, float& lo, float& hi) {
    asm("mov.b64 {%0, %1}, %2;" : "=f"(lo), "=f"(hi) : "l"(x));
}
__device__ __forceinline__ u64 f2fma(u64 a, u64 b, u64 c) {
    u64 d; asm("fma.rn.f32x2 %0, %1, %2, %3;" : "=l"(d) : "l"(a), "l"(b), "l"(c)); return d;
}
__device__ __forceinline__ u64 f2add(u64 a, u64 b) {
    u64 d; asm("add.rn.f32x2 %0, %1, %2;" : "=l"(d) : "l"(a), "l"(b)); return d;
}
__device__ __forceinline__ u64 f2mul(u64 a, u64 b) {
    u64 d; asm("mul.rn.f32x2 %0, %1, %2;" : "=l"(d) : "l"(a), "l"(b)); return d;
}

constexpr int B_SIZE  = 65536;
constexpr int T_STEPS = 512;
constexpr int THREADS = 64;               // 2 warps/block -> 512 blocks -> smoother SM balance
constexpr int WARPS   = THREADS / 32;

// Bloch RHS (params[:,1] unused, matching reference):
//   du = -g*u
//   dv = -g*v - Om*w
//   dw = -2g*(w+1) + Om*v  =  Om*v + (-2g)*w + (-2g)
//
// One thread integrates 2 adjacent particles packed into f32x2 lanes.
// Stores are staged through SMEM per-warp and written as coalesced STG.128.
__global__ __launch_bounds__(THREADS) void bloch_rk4_kernel(
    const float* __restrict__ y0,
    const float* __restrict__ t_span,
    const float* __restrict__ params,
    float* __restrict__ out)
{
    __shared__ float  s_dt[T_STEPS - 1];
    __shared__ float4 s_stage[2][WARPS][48];   // per-warp 768B staging, double-buffered

    for (int i = threadIdx.x; i < T_STEPS - 1; i += THREADS)
        s_dt[i] = t_span[i + 1] - t_span[i];
    __syncthreads();

    const int tid    = blockIdx.x * THREADS + threadIdx.x;
    const int lane   = threadIdx.x & 31;
    const int warpId = threadIdx.x >> 5;
    const int gwarp  = (blockIdx.x * THREADS + threadIdx.x) >> 5;  // global warp index
    const int base   = tid * 2;               // first of this thread's 2 particles

    // Load y0 (6 floats, 8B-aligned) and params (6 floats) as float2
    const float2* y02 = (const float2*)(y0 + (size_t)base * 3);
    float2 a0 = y02[0], a1 = y02[1], a2 = y02[2];
    const float2* pp  = (const float2*)(params + (size_t)base * 3);
    float2 p0 = pp[0], p1 = pp[1], p2 = pp[2];
    // particle0: u=a0.x v=a0.y w=a1.x  Om=p0.x g=p1.x
    // particle1: u=a1.y v=a2.x w=a2.y  Om=p1.y g=p2.y

    u64 u   = pk2(a0.x, a1.y);
    u64 v   = pk2(a0.y, a2.x);
    u64 w   = pk2(a1.x, a2.y);
    u64 Om  = pk2(p0.x, p1.y);
    u64 mOm = pk2(-p0.x, -p1.y);
    u64 ng  = pk2(-p1.x, -p2.y);               // -gamma
    u64 tg  = pk2(-2.0f * p1.x, -2.0f * p2.y); // -2*gamma (slope AND constant term)
    const u64 TWO = pk2(2.0f, 2.0f);

    // t = 0 row: passthrough copy of y0 (one-time, small)
    {
        float2* o = (float2*)(out + (size_t)base * 3);
        o[0] = a0; o[1] = a1; o[2] = a2;
    }

    // each warp owns a contiguous 192-float (48 x float4) chunk of every row
    float2* my_stage0 = (float2*)&s_stage[0][warpId][0] + lane * 3;
    float2* my_stage1 = (float2*)&s_stage[1][warpId][0] + lane * 3;

    for (int t = 0; t < T_STEPS - 1; t++) {
        const float dt = s_dt[t];
        const float h  = 0.5f * dt;
        const float d6 = dt * (1.0f / 6.0f);
        const u64 DT = pk2(dt, dt);
        const u64 H  = pk2(h,  h);
        const u64 D6 = pk2(d6, d6);

        // k1 = f(y)
        u64 k1u = f2mul(ng, u);
        u64 k1v = f2fma(ng, v, f2mul(mOm, w));
        u64 k1w = f2fma(Om, v, f2fma(tg, w, tg));
        // k2 = f(y + h*k1)
        u64 u2 = f2fma(H, k1u, u);
        u64 v2 = f2fma(H, k1v, v);
        u64 w2 = f2fma(H, k1w, w);
        u64 k2u = f2mul(ng, u2);
        u64 k2v = f2fma(ng, v2, f2mul(mOm, w2));
        u64 k2w = f2fma(Om, v2, f2fma(tg, w2, tg));
        // k3 = f(y + h*k2)
        u64 u3 = f2fma(H, k2u, u);
        u64 v3 = f2fma(H, k2v, v);
        u64 w3 = f2fma(H, k2w, w);
        u64 k3u = f2mul(ng, u3);
        u64 k3v = f2fma(ng, v3, f2mul(mOm, w3));
        u64 k3w = f2fma(Om, v3, f2fma(tg, w3, tg));
        // k4 = f(y + dt*k3)
        u64 u4 = f2fma(DT, k3u, u);
        u64 v4 = f2fma(DT, k3v, v);
        u64 w4 = f2fma(DT, k3w, w);
        u64 k4u = f2mul(ng, u4);
        u64 k4v = f2fma(ng, v4, f2mul(mOm, w4));
        u64 k4w = f2fma(Om, v4, f2fma(tg, w4, tg));

        // y += dt/6 * (k1 + 2*(k2+k3) + k4)
        u64 su = f2fma(TWO, f2add(k2u, k3u), f2add(k1u, k4u));
        u64 sv = f2fma(TWO, f2add(k2v, k3v), f2add(k1v, k4v));
        u64 sw = f2fma(TWO, f2add(k2w, k3w), f2add(k1w, k4w));
        u = f2fma(D6, su, u);
        v = f2fma(D6, sv, v);
        w = f2fma(D6, sw, w);

        // ---- staged coalesced store ----
        float uu0, uu1, vv0, vv1, ww0, ww1;
        upk2(u, uu0, uu1);
        upk2(v, vv0, vv1);
        upk2(w, ww0, ww1);

        float2* st = (t & 1) ? my_stage1 : my_stage0;
        st[0] = make_float2(uu0, vv0);
        st[1] = make_float2(ww0, uu1);
        st[2] = make_float2(vv1, ww1);
        __syncwarp();

        const float4* sbuf = &s_stage[t & 1][warpId][0];
        float4* gout = (float4*)(out + (size_t)B_SIZE * 3 * (t + 1)) + (size_t)gwarp * 48;
        __stcs(gout + lane, sbuf[lane]);
        if (lane < 16)
            __stcs(gout + 32 + lane, sbuf[32 + lane]);
        // double buffer: next iteration writes the other buffer, so the
        // single syncwarp per step is sufficient (WAR separated by 2 syncs).
    }
}

extern "C" void kernel_launch(void* const* d_in, const int* in_sizes, int n_in,
                              void* d_out, int out_size) {
    const float* y0     = (const float*)d_in[0];
    const float* t_span = (const float*)d_in[1];
    const float* params = (const float*)d_in[2];
    float* out          = (float*)d_out;

    const int total_threads = B_SIZE / 2;          // 32768 (2 particles/thread)
    const int grid = total_threads / THREADS;      // 512 blocks of 64 threads
    bloch_rk4_kernel<<<grid, THREADS>>>(y0, t_span, params, out);
}